// round 2
// baseline (speedup 1.0000x reference)
#include <cuda_runtime.h>

#define T_STEPS 48
#define B_SZ    512
#define D_SZ    1024
#define H_SZ    1024
#define G4      (4 * H_SZ)

// ---------------- scratch (static device globals; no allocation) ----------
__device__ float g_pooled[B_SZ * D_SZ];                       // 2 MB
__device__ float g_Gpool [B_SZ * G4];                         // 8 MB
__device__ float g_Gin   [(size_t)(T_STEPS - 1) * B_SZ * G4]; // ~386 MB
__device__ float g_gates [B_SZ * G4];                         // 8 MB
__device__ float g_h     [B_SZ * H_SZ];                       // 2 MB
__device__ float g_c     [B_SZ * H_SZ];                       // 2 MB

// ---------------- pooled mean over masked timesteps -----------------------
// captions: int32 (JAX default config downcasts the requested int64)
__global__ void pooled_kernel(const float* __restrict__ dh,
                              const int* __restrict__ cap,
                              float* __restrict__ pooled)
{
    int b = blockIdx.y;
    int d = blockIdx.x * blockDim.x + threadIdx.x;
    float acc = 0.f, len = 0.f;
    #pragma unroll
    for (int t = 0; t < T_STEPS; t++) {
        int v = cap[t * B_SZ + b];
        float m = (v != 0 && v != 2) ? 1.f : 0.f;
        len += m;
        acc += m * dh[(size_t)t * B_SZ * D_SZ + (size_t)b * D_SZ + d];
    }
    pooled[(size_t)b * D_SZ + d] = acc / len;
}

// ---------------- zero h, c, and out[:, 0, :] ------------------------------
__global__ void init_kernel(float* __restrict__ h, float* __restrict__ c,
                            float* __restrict__ out)
{
    int idx = blockIdx.x * blockDim.x + threadIdx.x;  // over B*H
    h[idx] = 0.f;
    c[idx] = 0.f;
    int b = idx >> 10;        // / H_SZ
    int j = idx & 1023;       // % H_SZ
    out[(size_t)b * T_STEPS * H_SZ + j] = 0.f;
}

// ---------------- generic C = A @ W^T (+add)(+bias1)(+bias2) ---------------
// A: [M, K] row-major (lda), W: [N, K] row-major (ldw), C: [M, N].
// add: if non-null, adds add[(add_mod ? m % add_mod : m) * N + n].
// Tiling: 128x128x8, 256 threads, 8x8 per thread. All dims assumed multiples.
__global__ __launch_bounds__(256, 2)
void gemm_nt(const float* __restrict__ A, int lda,
             const float* __restrict__ W, int ldw,
             const float* __restrict__ add, int add_mod,
             const float* __restrict__ bias1,
             const float* __restrict__ bias2,
             float* __restrict__ C, int N, int K)
{
    __shared__ float As[8][128];
    __shared__ float Bs[8][128];

    const int tid = threadIdx.x;
    const int m0  = blockIdx.y * 128;
    const int n0  = blockIdx.x * 128;
    const int tx  = tid & 15;   // n sub-tile
    const int ty  = tid >> 4;   // m sub-tile

    const int lrow = tid >> 1;        // 0..127
    const int lc4  = (tid & 1) * 4;   // 0 or 4

    const float* Aptr = A + (size_t)(m0 + lrow) * lda + lc4;
    const float* Wptr = W + (size_t)(n0 + lrow) * ldw + lc4;

    float acc[8][8];
    #pragma unroll
    for (int i = 0; i < 8; i++)
        #pragma unroll
        for (int j = 0; j < 8; j++) acc[i][j] = 0.f;

    for (int k0 = 0; k0 < K; k0 += 8) {
        float4 av = *(const float4*)(Aptr + k0);
        float4 wv = *(const float4*)(Wptr + k0);
        As[lc4 + 0][lrow] = av.x;
        As[lc4 + 1][lrow] = av.y;
        As[lc4 + 2][lrow] = av.z;
        As[lc4 + 3][lrow] = av.w;
        Bs[lc4 + 0][lrow] = wv.x;
        Bs[lc4 + 1][lrow] = wv.y;
        Bs[lc4 + 2][lrow] = wv.z;
        Bs[lc4 + 3][lrow] = wv.w;
        __syncthreads();

        #pragma unroll
        for (int kk = 0; kk < 8; kk++) {
            float af[8], bf[8];
            *(float4*)&af[0] = *(const float4*)&As[kk][ty * 8];
            *(float4*)&af[4] = *(const float4*)&As[kk][ty * 8 + 4];
            *(float4*)&bf[0] = *(const float4*)&Bs[kk][tx * 8];
            *(float4*)&bf[4] = *(const float4*)&Bs[kk][tx * 8 + 4];
            #pragma unroll
            for (int i = 0; i < 8; i++)
                #pragma unroll
                for (int j = 0; j < 8; j++)
                    acc[i][j] += af[i] * bf[j];
        }
        __syncthreads();
    }

    #pragma unroll
    for (int i = 0; i < 8; i++) {
        const int m  = m0 + ty * 8 + i;
        const int am = add_mod ? (m % add_mod) : m;
        #pragma unroll
        for (int j = 0; j < 8; j++) {
            const int n = n0 + tx * 8 + j;
            float v = acc[i][j];
            if (add)   v += add[(size_t)am * N + n];
            if (bias1) v += bias1[n];
            if (bias2) v += bias2[n];
            C[(size_t)m * N + n] = v;
        }
    }
}

// ---------------- LSTM pointwise: gates -> (h, c), write output ------------
__global__ void lstm_act(const float* __restrict__ gates,
                         float* __restrict__ h, float* __restrict__ c,
                         float* __restrict__ out, int t)
{
    int idx = blockIdx.x * blockDim.x + threadIdx.x;  // over B*H
    int b = idx >> 10;
    int j = idx & 1023;
    const float* gb = gates + (size_t)b * G4;
    float xi = gb[j];
    float xf = gb[H_SZ + j];
    float xg = gb[2 * H_SZ + j];
    float xo = gb[3 * H_SZ + j];
    float ig = 1.f / (1.f + expf(-xi));
    float fg = 1.f / (1.f + expf(-xf));
    float gg = tanhf(xg);
    float og = 1.f / (1.f + expf(-xo));
    float cn = fg * c[idx] + ig * gg;
    c[idx] = cn;
    float hn = og * tanhf(cn);
    h[idx] = hn;
    out[(size_t)b * T_STEPS * H_SZ + (size_t)t * H_SZ + j] = hn;
}

// ---------------------------------------------------------------------------
extern "C" void kernel_launch(void* const* d_in, const int* in_sizes, int n_in,
                              void* d_out, int out_size)
{
    const float* dh    = (const float*)d_in[0];      // [T,1,B,D] == [T,B,D]
    // d_in[1] ("outputs") is unused by the reference
    const int*   cap   = (const int*)d_in[2];        // [T,B] int32 (JAX default)
    const float* W_ih  = (const float*)d_in[3];      // [4H, 2D]
    const float* W_hh  = (const float*)d_in[4];      // [4H, H]
    const float* b_ih  = (const float*)d_in[5];      // [4H]
    const float* b_hh  = (const float*)d_in[6];      // [4H]
    float*       out   = (float*)d_out;              // [B, T, H]

    float *pooled, *Gpool, *Gin, *gates, *h, *c;
    cudaGetSymbolAddress((void**)&pooled, g_pooled);
    cudaGetSymbolAddress((void**)&Gpool,  g_Gpool);
    cudaGetSymbolAddress((void**)&Gin,    g_Gin);
    cudaGetSymbolAddress((void**)&gates,  g_gates);
    cudaGetSymbolAddress((void**)&h,      g_h);
    cudaGetSymbolAddress((void**)&c,      g_c);

    // 1) pooled mean over masked timesteps
    pooled_kernel<<<dim3(D_SZ / 256, B_SZ), 256>>>(dh, cap, pooled);

    // 2) zero h, c, out[:,0,:]
    init_kernel<<<(B_SZ * H_SZ) / 256, 256>>>(h, c, out);

    // 3) Gpool[b, 4H] = pooled @ W_ih[:, D:]^T + b_ih + b_hh   (constant across t)
    gemm_nt<<<dim3(G4 / 128, B_SZ / 128), 256>>>(
        pooled, D_SZ, W_ih + D_SZ, 2 * D_SZ,
        nullptr, 0, b_ih, b_hh, Gpool, G4, D_SZ);

    // 4) Gin[t-1, b, 4H] = dh[t] @ W_ih[:, :D]^T + Gpool[b]   (one big parallel GEMM)
    gemm_nt<<<dim3(G4 / 128, ((T_STEPS - 1) * B_SZ) / 128), 256>>>(
        dh + (size_t)B_SZ * D_SZ, D_SZ, W_ih, 2 * D_SZ,
        Gpool, B_SZ, nullptr, nullptr, Gin, G4, D_SZ);

    // 5) recurrence: gates = h @ W_hh^T + Gin[t];  pointwise LSTM update
    for (int t = 1; t < T_STEPS; t++) {
        gemm_nt<<<dim3(G4 / 128, B_SZ / 128), 256>>>(
            h, H_SZ, W_hh, H_SZ,
            Gin + (size_t)(t - 1) * B_SZ * G4, 0, nullptr, nullptr,
            gates, G4, H_SZ);
        lstm_act<<<(B_SZ * H_SZ) / 256, 256>>>(gates, h, c, out, t);
    }
}

// round 4
// speedup vs baseline: 1.7146x; 1.7146x over previous
#include <cuda_runtime.h>
#include <cstdint>

#define T_STEPS 48
#define B_SZ    512
#define D_SZ    1024
#define H_SZ    1024
#define G4      (4 * H_SZ)

// ---------------- scratch (static device globals; no allocation) ----------
__device__ float g_pooled[B_SZ * D_SZ];                       // 2 MB
__device__ float g_Gpool [B_SZ * G4];                         // 8 MB
__device__ float g_Gin   [(size_t)(T_STEPS - 1) * B_SZ * G4]; // ~386 MB
__device__ float g_gates [B_SZ * G4];                         // 8 MB
__device__ float g_h     [B_SZ * H_SZ];                       // 2 MB
__device__ float g_c     [B_SZ * H_SZ];                       // 2 MB

// ===================== helpers =============================================
__device__ __forceinline__ float tf32_round(float x) {
    float y; asm("cvt.rna.tf32.f32 %0, %1;" : "=f"(y) : "f"(x)); return y;
}

// mma.sync m16n8k8 tf32: D += A*B (row.col), fp32 accumulate
#define MMA_TF32(d, a, b)                                                     \
    asm volatile(                                                             \
        "mma.sync.aligned.m16n8k8.row.col.f32.tf32.tf32.f32 "                 \
        "{%0,%1,%2,%3}, {%4,%5,%6,%7}, {%8,%9}, {%0,%1,%2,%3};"               \
        : "+f"((d)[0]), "+f"((d)[1]), "+f"((d)[2]), "+f"((d)[3])              \
        : "r"((a)[0]), "r"((a)[1]), "r"((a)[2]), "r"((a)[3]),                 \
          "r"((b)[0]), "r"((b)[1]))

// ===================== tensor-core tf32 split-fp32 GEMM ====================
// C[M,N] = A[M,K] @ W[N,K]^T (+add)(+bias1)(+bias2)
// CTA tile 128x128, BK=32, 8 warps (2x4), warp tile 64x32.
// Split: x = hi + lo; D += Ah*Bh + Ah*Bl + Al*Bh  (err ~2^-21).
#define BK       32
#define SSTRIDE  36   // floats; (4g+t)%32 distinct -> conflict-free frags; 16B aligned
#define TILE_F   (128 * SSTRIDE)
#define SMEM_F   (4 * TILE_F)                  // AsH, AsL, BsH, BsL
#define SMEM_B   (SMEM_F * 4)                  // 73728 bytes

__global__ __launch_bounds__(256)
void gemm_mma(const float* __restrict__ A, int lda,
              const float* __restrict__ W, int ldw,
              const float* __restrict__ add, int add_mod,
              const float* __restrict__ bias1, const float* __restrict__ bias2,
              float* __restrict__ C, int N, int K)
{
    extern __shared__ float sm[];
    float* AsH = sm;
    float* AsL = sm + TILE_F;
    float* BsH = sm + 2 * TILE_F;
    float* BsL = sm + 3 * TILE_F;

    const int tid = threadIdx.x;
    const int wid = tid >> 5, lid = tid & 31;
    const int wm  = wid >> 2, wn = wid & 3;       // 2x4 warp grid
    const int g   = lid >> 2, t  = lid & 3;       // mma lane decomposition
    const int m0  = blockIdx.y * 128;
    const int n0  = blockIdx.x * 128;

    // loader mapping: 256 threads cover 128 rows x 8 float4 (32 cols)
    const int j  = tid & 7;     // float4 column
    const int r0 = tid >> 3;    // 0..31, rows r0 + 32*rr

    float acc[4][4][4];
    #pragma unroll
    for (int a_ = 0; a_ < 4; a_++)
        #pragma unroll
        for (int b_ = 0; b_ < 4; b_++)
            #pragma unroll
            for (int e = 0; e < 4; e++) acc[a_][b_][e] = 0.f;

    const float* Abase = A + (size_t)(m0 + r0) * lda + j * 4;
    const float* Wbase = W + (size_t)(n0 + r0) * ldw + j * 4;

    float4 pa[4], pw[4];
    #pragma unroll
    for (int rr = 0; rr < 4; rr++) {
        pa[rr] = *(const float4*)(Abase + (size_t)rr * 32 * lda);
        pw[rr] = *(const float4*)(Wbase + (size_t)rr * 32 * ldw);
    }

    const int KT = K / BK;
    for (int kt = 0; kt < KT; kt++) {
        __syncthreads();   // previous compute done before overwriting smem
        #pragma unroll
        for (int rr = 0; rr < 4; rr++) {
            const int r = r0 + rr * 32;
            float4 v = pa[rr], hi, lo;
            hi.x = tf32_round(v.x); lo.x = tf32_round(v.x - hi.x);
            hi.y = tf32_round(v.y); lo.y = tf32_round(v.y - hi.y);
            hi.z = tf32_round(v.z); lo.z = tf32_round(v.z - hi.z);
            hi.w = tf32_round(v.w); lo.w = tf32_round(v.w - hi.w);
            *(float4*)(AsH + r * SSTRIDE + j * 4) = hi;
            *(float4*)(AsL + r * SSTRIDE + j * 4) = lo;
            v = pw[rr];
            hi.x = tf32_round(v.x); lo.x = tf32_round(v.x - hi.x);
            hi.y = tf32_round(v.y); lo.y = tf32_round(v.y - hi.y);
            hi.z = tf32_round(v.z); lo.z = tf32_round(v.z - hi.z);
            hi.w = tf32_round(v.w); lo.w = tf32_round(v.w - hi.w);
            *(float4*)(BsH + r * SSTRIDE + j * 4) = hi;
            *(float4*)(BsL + r * SSTRIDE + j * 4) = lo;
        }
        __syncthreads();

        if (kt + 1 < KT) {   // prefetch next k-slab; overlaps with MMA below
            const int ko = (kt + 1) * BK;
            #pragma unroll
            for (int rr = 0; rr < 4; rr++) {
                pa[rr] = *(const float4*)(Abase + (size_t)rr * 32 * lda + ko);
                pw[rr] = *(const float4*)(Wbase + (size_t)rr * 32 * ldw + ko);
            }
        }

        #pragma unroll
        for (int ks = 0; ks < 4; ks++) {
            uint32_t ah[4][4], al[4][4], bh[4][2], bl[4][2];
            #pragma unroll
            for (int mt = 0; mt < 4; mt++) {
                const float* p = AsH + (wm * 64 + mt * 16 + g) * SSTRIDE + ks * 8 + t;
                ah[mt][0] = __float_as_uint(p[0]);
                ah[mt][1] = __float_as_uint(p[8 * SSTRIDE]);
                ah[mt][2] = __float_as_uint(p[4]);
                ah[mt][3] = __float_as_uint(p[8 * SSTRIDE + 4]);
            }
            #pragma unroll
            for (int nt = 0; nt < 4; nt++) {
                const float* p = BsH + (wn * 32 + nt * 8 + g) * SSTRIDE + ks * 8 + t;
                bh[nt][0] = __float_as_uint(p[0]);
                bh[nt][1] = __float_as_uint(p[4]);
            }
            #pragma unroll
            for (int mt = 0; mt < 4; mt++)
                #pragma unroll
                for (int nt = 0; nt < 4; nt++)
                    MMA_TF32(acc[mt][nt], ah[mt], bh[nt]);

            #pragma unroll
            for (int nt = 0; nt < 4; nt++) {
                const float* p = BsL + (wn * 32 + nt * 8 + g) * SSTRIDE + ks * 8 + t;
                bl[nt][0] = __float_as_uint(p[0]);
                bl[nt][1] = __float_as_uint(p[4]);
            }
            #pragma unroll
            for (int mt = 0; mt < 4; mt++)
                #pragma unroll
                for (int nt = 0; nt < 4; nt++)
                    MMA_TF32(acc[mt][nt], ah[mt], bl[nt]);

            #pragma unroll
            for (int mt = 0; mt < 4; mt++) {
                const float* p = AsL + (wm * 64 + mt * 16 + g) * SSTRIDE + ks * 8 + t;
                al[mt][0] = __float_as_uint(p[0]);
                al[mt][1] = __float_as_uint(p[8 * SSTRIDE]);
                al[mt][2] = __float_as_uint(p[4]);
                al[mt][3] = __float_as_uint(p[8 * SSTRIDE + 4]);
            }
            #pragma unroll
            for (int mt = 0; mt < 4; mt++)
                #pragma unroll
                for (int nt = 0; nt < 4; nt++)
                    MMA_TF32(acc[mt][nt], al[mt], bh[nt]);
        }
    }

    // -------- epilogue: fuse add / bias, write fp32 --------
    #pragma unroll
    for (int mt = 0; mt < 4; mt++) {
        const int row  = m0 + wm * 64 + mt * 16 + g;
        const int row2 = row + 8;
        const int am   = add_mod ? (row  % add_mod) : row;
        const int am2  = add_mod ? (row2 % add_mod) : row2;
        #pragma unroll
        for (int nt = 0; nt < 4; nt++) {
            const int col = n0 + wn * 32 + nt * 8 + 2 * t;
            float v0 = acc[mt][nt][0], v1 = acc[mt][nt][1];
            float v2 = acc[mt][nt][2], v3 = acc[mt][nt][3];
            if (add) {
                v0 += add[(size_t)am  * N + col];
                v1 += add[(size_t)am  * N + col + 1];
                v2 += add[(size_t)am2 * N + col];
                v3 += add[(size_t)am2 * N + col + 1];
            }
            if (bias1) {
                v0 += bias1[col]; v1 += bias1[col + 1];
                v2 += bias1[col]; v3 += bias1[col + 1];
            }
            if (bias2) {
                v0 += bias2[col]; v1 += bias2[col + 1];
                v2 += bias2[col]; v3 += bias2[col + 1];
            }
            *(float2*)(C + (size_t)row  * N + col) = make_float2(v0, v1);
            *(float2*)(C + (size_t)row2 * N + col) = make_float2(v2, v3);
        }
    }
}

// ---------------- pooled mean over masked timesteps -----------------------
__global__ void pooled_kernel(const float* __restrict__ dh,
                              const int* __restrict__ cap,
                              float* __restrict__ pooled)
{
    int b = blockIdx.y;
    int d = blockIdx.x * blockDim.x + threadIdx.x;
    float acc = 0.f, len = 0.f;
    #pragma unroll
    for (int t = 0; t < T_STEPS; t++) {
        int v = cap[t * B_SZ + b];
        float m = (v != 0 && v != 2) ? 1.f : 0.f;
        len += m;
        acc += m * dh[(size_t)t * B_SZ * D_SZ + (size_t)b * D_SZ + d];
    }
    pooled[(size_t)b * D_SZ + d] = acc / len;
}

// ---------------- zero h, c, and out[:, 0, :] ------------------------------
__global__ void init_kernel(float* __restrict__ h, float* __restrict__ c,
                            float* __restrict__ out)
{
    int idx = blockIdx.x * blockDim.x + threadIdx.x;
    h[idx] = 0.f;
    c[idx] = 0.f;
    int b = idx >> 10;
    int j = idx & 1023;
    out[(size_t)b * T_STEPS * H_SZ + j] = 0.f;
}

// ---------------- LSTM pointwise: gates -> (h, c), write output ------------
__global__ void lstm_act(const float* __restrict__ gates,
                         float* __restrict__ h, float* __restrict__ c,
                         float* __restrict__ out, int t)
{
    int idx = blockIdx.x * blockDim.x + threadIdx.x;
    int b = idx >> 10;
    int j = idx & 1023;
    const float* gb = gates + (size_t)b * G4;
    float xi = gb[j];
    float xf = gb[H_SZ + j];
    float xg = gb[2 * H_SZ + j];
    float xo = gb[3 * H_SZ + j];
    float ig = 1.f / (1.f + expf(-xi));
    float fg = 1.f / (1.f + expf(-xf));
    float gg = tanhf(xg);
    float og = 1.f / (1.f + expf(-xo));
    float cn = fg * c[idx] + ig * gg;
    c[idx] = cn;
    float hn = og * tanhf(cn);
    h[idx] = hn;
    out[(size_t)b * T_STEPS * H_SZ + (size_t)t * H_SZ + j] = hn;
}

// ---------------------------------------------------------------------------
extern "C" void kernel_launch(void* const* d_in, const int* in_sizes, int n_in,
                              void* d_out, int out_size)
{
    const float* dh    = (const float*)d_in[0];      // [T,1,B,D] == [T,B,D]
    const int*   cap   = (const int*)d_in[2];        // [T,B] int32
    const float* W_ih  = (const float*)d_in[3];      // [4H, 2D]
    const float* W_hh  = (const float*)d_in[4];      // [4H, H]
    const float* b_ih  = (const float*)d_in[5];      // [4H]
    const float* b_hh  = (const float*)d_in[6];      // [4H]
    float*       out   = (float*)d_out;              // [B, T, H]

    float *pooled, *Gpool, *Gin, *gates, *h, *c;
    cudaGetSymbolAddress((void**)&pooled, g_pooled);
    cudaGetSymbolAddress((void**)&Gpool,  g_Gpool);
    cudaGetSymbolAddress((void**)&Gin,    g_Gin);
    cudaGetSymbolAddress((void**)&gates,  g_gates);
    cudaGetSymbolAddress((void**)&h,      g_h);
    cudaGetSymbolAddress((void**)&c,      g_c);

    cudaFuncSetAttribute(gemm_mma, cudaFuncAttributeMaxDynamicSharedMemorySize, SMEM_B);

    // 1) pooled mean over masked timesteps
    pooled_kernel<<<dim3(D_SZ / 256, B_SZ), 256>>>(dh, cap, pooled);

    // 2) zero h, c, out[:,0,:]
    init_kernel<<<(B_SZ * H_SZ) / 256, 256>>>(h, c, out);

    // 3) Gpool = pooled @ W_ih[:, D:]^T + b_ih + b_hh   (constant across t)
    gemm_mma<<<dim3(G4 / 128, B_SZ / 128), 256, SMEM_B>>>(
        pooled, D_SZ, W_ih + D_SZ, 2 * D_SZ,
        nullptr, 0, b_ih, b_hh, Gpool, G4, D_SZ);

    // 4) Gin[t-1] = dh[t] @ W_ih[:, :D]^T + Gpool       (one big parallel GEMM)
    gemm_mma<<<dim3(G4 / 128, ((T_STEPS - 1) * B_SZ) / 128), 256, SMEM_B>>>(
        dh + (size_t)B_SZ * D_SZ, D_SZ, W_ih, 2 * D_SZ,
        Gpool, B_SZ, nullptr, nullptr, Gin, G4, D_SZ);

    // 5) recurrence: gates = h @ W_hh^T + Gin[t]; pointwise LSTM update
    for (int t = 1; t < T_STEPS; t++) {
        gemm_mma<<<dim3(G4 / 128, B_SZ / 128), 256, SMEM_B>>>(
            h, H_SZ, W_hh, H_SZ,
            Gin + (size_t)(t - 1) * B_SZ * G4, 0, nullptr, nullptr,
            gates, G4, H_SZ);
        lstm_act<<<(B_SZ * H_SZ) / 256, 256>>>(gates, h, c, out, t);
    }
}